// round 1
// baseline (speedup 1.0000x reference)
#include <cuda_runtime.h>
#include <cstdint>

#define NUM_STEPS 180
#define Bb 2
#define Hh 512
#define Ww 512
#define HW (Hh*Ww)
#define Dd 128
#define Vv (Dd*Dd*Dd)

// Scratch: template repacked as float4 per voxel (c0,c1,c2,c3), per batch.
__device__ float4 g_tpl[Bb*Vv];                 // 67 MB
__device__ uint2  g_keys[NUM_STEPS+1];          // fold_in(key42, i), i=0..180
__device__ unsigned int g_len_min_bits, g_len_max_bits;

__device__ __forceinline__ uint32_t rotl32(uint32_t x, int r){ return __funnelshift_l(x, x, r); }

// JAX threefry2x32 (20 rounds, rotations [13,15,26,6]/[17,29,16,24], C=0x1BD11BDA)
__device__ __forceinline__ uint2 tf2x32(uint32_t k0, uint32_t k1, uint32_t x0, uint32_t x1){
  uint32_t k2 = k0 ^ k1 ^ 0x1BD11BDAu;
  x0 += k0; x1 += k1;
#define TFR(r) { x0 += x1; x1 = rotl32(x1, (r)); x1 ^= x0; }
  TFR(13) TFR(15) TFR(26) TFR(6)
  x0 += k1; x1 += k2 + 1u;
  TFR(17) TFR(29) TFR(16) TFR(24)
  x0 += k2; x1 += k0 + 2u;
  TFR(13) TFR(15) TFR(26) TFR(6)
  x0 += k0; x1 += k1 + 3u;
  TFR(17) TFR(29) TFR(16) TFR(24)
  x0 += k1; x1 += k2 + 4u;
  TFR(13) TFR(15) TFR(26) TFR(6)
  x0 += k2; x1 += k0 + 5u;
#undef TFR
  return make_uint2(x0, x1);
}

__global__ void k_setup(){
  int i = threadIdx.x;
  if (i <= NUM_STEPS) g_keys[i] = tf2x32(0u, 42u, 0u, (uint32_t)i);  // fold_in(key(42), i)
  if (i == 0){ g_len_min_bits = 0x7F800000u; g_len_max_bits = 0u; }
}

// (B,4,D,D,D) -> (B, D^3, float4)
__global__ void k_pack(const float* __restrict__ tpl){
  int v = blockIdx.x*256 + threadIdx.x;     // 0 .. Bb*Vv-1
  int b = v >> 21;                          // Vv = 2^21
  int r = v & (Vv-1);
  const float* base = tpl + (size_t)b*4*Vv;
  g_tpl[v] = make_float4(base[r], base[Vv+r], base[2*Vv+r], base[3*Vv+r]);
}

__global__ __launch_bounds__(128) void k_march(
  const float* __restrict__ rot, const float* __restrict__ campos,
  const float* __restrict__ fo,  const float* __restrict__ pp,
  const float* __restrict__ bg,  float* __restrict__ out)
{
  __shared__ uint2 skeys[NUM_STEPS+1];
  int lt = threadIdx.y*16 + threadIdx.x;
  for (int i = lt; i <= NUM_STEPS; i += 128) skeys[i] = g_keys[i];
  __syncthreads();

  int w = blockIdx.x*16 + threadIdx.x;
  int h = blockIdx.y*8  + threadIdx.y;
  int b = blockIdx.z;
  int p = b*HW + h*Ww + w;                  // flat index over (B,H,W)

  // ray direction: rd = R^T * [(w-cx)/fx, (h-cy)/fy, 1], normalized
  float rx = ((float)w - pp[2*b+0]) / fo[2*b+0];
  float ry = ((float)h - pp[2*b+1]) / fo[2*b+1];
  const float* R = rot + 9*b;
  float dx = R[0]*rx + R[3]*ry + R[6];
  float dy = R[1]*rx + R[4]*ry + R[7];
  float dz = R[2]*rx + R[5]*ry + R[8];
  float nrm = sqrtf(dx*dx + dy*dy + dz*dz);
  dx /= nrm; dy /= nrm; dz /= nrm;
  float cxp = campos[3*b+0], cyp = campos[3*b+1], czp = campos[3*b+2];

  // AABB [-1,1]^3 intersection
  float t1x = (-1.0f-cxp)/dx, t2x = (1.0f-cxp)/dx;
  float t1y = (-1.0f-cyp)/dy, t2y = (1.0f-cyp)/dy;
  float t1z = (-1.0f-czp)/dz, t2z = (1.0f-czp)/dz;
  float tmin = fmaxf(fminf(t1x,t2x), fmaxf(fminf(t1y,t2y), fminf(t1z,t2z)));
  float tmax = fminf(fmaxf(t1x,t2x), fminf(fmaxf(t1y,t2y), fmaxf(t1z,t2z)));
  float t = (tmin < tmax) ? tmin : 0.0f;
  t = fmaxf(t, 0.0f);

  // t jitter: uniform(fold_in(key,0)) -- partitionable bits = o0^o1 of tf(key,(0,p))
  {
    uint2 o = tf2x32(skeys[0].x, skeys[0].y, 0u, (uint32_t)p);
    uint32_t bits = o.x ^ o.y;
    float u = __uint_as_float((bits >> 9) | 0x3f800000u) - 1.0f;
    t = t - 0.02f * u;
  }

  float px = cxp + dx*t, py = cyp + dy*t, pz = czp + dz*t;
  float r0_=0.f, r1_=0.f, r2_=0.f, al=0.f, len=0.f;
  const float4* tp = g_tpl + (size_t)b*Vv;
  const float LO = -0.99999994f;            // nextafterf(-1,0)

  for (int i = 0; i < NUM_STEPS; i++){
    // noise = sqrt(2)*erfinv(uniform(lo,1)) with key fold_in(key, i+1)
    uint2 key = skeys[i+1];
    uint2 o = tf2x32(key.x, key.y, 0u, (uint32_t)p);
    uint32_t bits = o.x ^ o.y;
    float u01 = __uint_as_float((bits >> 9) | 0x3f800000u) - 1.0f;
    float uu = fmaxf(LO, u01 * 2.0f + LO);  // (hi-lo) rounds to exactly 2.0f
    float noise = 1.41421356f * erfinvf(uu);
    float stepv = 0.02f * expf(0.01f * noise);

    bool valid = (px > -1.0f) && (px < 1.0f) && (py > -1.0f) && (py < 1.0f)
              && (pz > -1.0f) && (pz < 1.0f);
    float contrib = 0.0f;
    if (valid && al < 1.0f){
      float gx = fminf(fmaxf((px+1.0f)*0.5f*127.0f, 0.0f), 127.0f);
      float gy = fminf(fmaxf((py+1.0f)*0.5f*127.0f, 0.0f), 127.0f);
      float gz = fminf(fmaxf((pz+1.0f)*0.5f*127.0f, 0.0f), 127.0f);
      int x0 = (int)floorf(gx); int x1 = min(x0+1,127); float wx = gx - (float)x0;
      int y0 = (int)floorf(gy); int y1 = min(y0+1,127); float wy = gy - (float)y0;
      int z0 = (int)floorf(gz); int z1 = min(z0+1,127); float wz = gz - (float)z0;
      int zy00 = (z0*Dd + y0)*Dd, zy01 = (z0*Dd + y1)*Dd;
      int zy10 = (z1*Dd + y0)*Dd, zy11 = (z1*Dd + y1)*Dd;
      float4 v000 = tp[zy00 + x0], v001 = tp[zy00 + x1];
      float4 v010 = tp[zy01 + x0], v011 = tp[zy01 + x1];
      float4 v100 = tp[zy10 + x0], v101 = tp[zy10 + x1];
      float4 v110 = tp[zy11 + x0], v111 = tp[zy11 + x1];
      float iwx = 1.0f - wx, iwy = 1.0f - wy, iwz = 1.0f - wz;
      float s0,s1,s2,s3;
#define TRI(ch, dst) { \
      float c00 = v000.ch*iwx + v001.ch*wx; \
      float c01 = v010.ch*iwx + v011.ch*wx; \
      float c10 = v100.ch*iwx + v101.ch*wx; \
      float c11 = v110.ch*iwx + v111.ch*wx; \
      float c0 = c00*iwy + c01*wy; \
      float c1 = c10*iwy + c11*wy; \
      dst = c0*iwz + c1*wz; }
      TRI(x,s0) TRI(y,s1) TRI(z,s2) TRI(w,s3)
#undef TRI
      contrib = fminf(al + s3*stepv, 1.0f) - al;
      r0_ += s0*contrib; r1_ += s1*contrib; r2_ += s2*contrib;
      al += contrib;
    }
    len += (contrib == 0.0f) ? stepv : 0.0f;
    px += dx*stepv; py += dy*stepv; pz += dz*stepv;
  }

  int pix = h*Ww + w;
  size_t rgbBase = (size_t)b*3*HW + pix;
  float ia = 1.0f - al;
  out[rgbBase       ] = r0_ + ia*fmaxf(bg[(size_t)(3*b+0)*HW + pix], 0.0f);
  out[rgbBase +   HW] = r1_ + ia*fmaxf(bg[(size_t)(3*b+1)*HW + pix], 0.0f);
  out[rgbBase + 2*HW] = r2_ + ia*fmaxf(bg[(size_t)(3*b+2)*HW + pix], 0.0f);
  out[(size_t)Bb*3*HW + b*HW + pix] = al;
  out[(size_t)Bb*4*HW + b*HW + pix] = len;   // raw; normalized by k_norm

  // global min/max of raw len (len >= 0, so uint bit order == float order)
  unsigned lb = __float_as_uint(len);
  unsigned mx = __reduce_max_sync(0xffffffffu, lb);
  unsigned mn = __reduce_min_sync(0xffffffffu, lb);
  if ((lt & 31) == 0){ atomicMax(&g_len_max_bits, mx); atomicMin(&g_len_min_bits, mn); }
}

__global__ void k_norm(float* __restrict__ out){
  int i = blockIdx.x*256 + threadIdx.x;     // < Bb*HW
  float denom = __uint_as_float(g_len_max_bits) + __uint_as_float(g_len_min_bits);
  float a = out[(size_t)Bb*3*HW + i];
  float l = out[(size_t)Bb*4*HW + i];
  out[(size_t)Bb*4*HW + i] = (a * l) / denom;
}

extern "C" void kernel_launch(void* const* d_in, const int* in_sizes, int n_in,
                              void* d_out, int out_size) {
  const float* rot    = (const float*)d_in[0];  // camera_rotation (B,3,3)
  const float* campos = (const float*)d_in[1];  // camera_position (B,3)
  const float* fo     = (const float*)d_in[2];  // focal (B,2)
  const float* pp     = (const float*)d_in[3];  // principal_point (B,2)
  // d_in[4] = pixel_coords (values are just (w,h) meshgrid; recomputed in-kernel)
  const float* tpl    = (const float*)d_in[5];  // template (B,4,D,D,D)
  const float* bg     = (const float*)d_in[6];  // background (B,3,H,W)
  float* out = (float*)d_out;

  k_setup<<<1, 256>>>();
  k_pack<<<(Bb*Vv)/256, 256>>>(tpl);
  dim3 blk(16,8,1), grd(Ww/16, Hh/8, Bb);
  k_march<<<grd, blk>>>(rot, campos, fo, pp, bg, out);
  k_norm<<<(Bb*HW)/256, 256>>>(out);
}